// round 2
// baseline (speedup 1.0000x reference)
#include <cuda_runtime.h>
#include <cstddef>

#define NN 100000
#define EE 1600000
#define NB_SCAN ((NN + 1023) / 1024)   // 98

// ---------------- device scratch (no allocations allowed) ----------------
__device__ int   d_indeg[NN];
__device__ float d_dinv[NN];
__device__ int   d_scan[NN];
__device__ int   d_bsum[128];
__device__ int   d_bexcl[128];
__device__ int   d_off[NN + 1];
__device__ int   d_cur[NN];
__device__ int   d_col[EE];
__device__ float d_hA[(size_t)NN * 128];
__device__ float d_hB[(size_t)NN * 128];

// ---------------- preprocessing ----------------
__global__ void deg_init_kernel() {
    int i = blockIdx.x * blockDim.x + threadIdx.x;
    if (i < NN) d_indeg[i] = 0;
}

__global__ void deg_count_kernel(const int* __restrict__ ei) {
    int e = blockIdx.x * blockDim.x + threadIdx.x;
    if (e < EE) atomicAdd(&d_indeg[ei[EE + e]], 1);
}

__global__ void dinv_kernel() {
    int i = blockIdx.x * blockDim.x + threadIdx.x;
    if (i < NN) d_dinv[i] = rsqrtf((float)(d_indeg[i] + 1));
}

// block-wise inclusive scan of indeg
__global__ void scan1_kernel() {
    __shared__ int sh[1024];
    int t = threadIdx.x;
    int i = blockIdx.x * 1024 + t;
    int v = (i < NN) ? d_indeg[i] : 0;
    sh[t] = v;
    __syncthreads();
    for (int s = 1; s < 1024; s <<= 1) {
        int add = (t >= s) ? sh[t - s] : 0;
        __syncthreads();
        sh[t] += add;
        __syncthreads();
    }
    if (i < NN) d_scan[i] = sh[t];
    if (t == 1023) d_bsum[blockIdx.x] = sh[1023];
}

// exclusive scan of block sums (single block)
__global__ void scan2_kernel() {
    __shared__ int sh[128];
    int t = threadIdx.x;
    int v = (t < NB_SCAN) ? d_bsum[t] : 0;
    sh[t] = v;
    __syncthreads();
    for (int s = 1; s < 128; s <<= 1) {
        int add = (t >= s) ? sh[t - s] : 0;
        __syncthreads();
        sh[t] += add;
        __syncthreads();
    }
    if (t < NB_SCAN) d_bexcl[t] = sh[t] - v;
}

__global__ void scan3_kernel() {
    int i = blockIdx.x * blockDim.x + threadIdx.x;
    if (i >= NN) return;
    int off = d_scan[i] - d_indeg[i] + d_bexcl[i >> 10];
    d_off[i] = off;
    d_cur[i] = off;
    if (i == NN - 1) d_off[NN] = off + d_indeg[i];
}

__global__ void fill_kernel(const int* __restrict__ ei) {
    int e = blockIdx.x * blockDim.x + threadIdx.x;
    if (e >= EE) return;
    int dst = ei[EE + e];
    int p = atomicAdd(&d_cur[dst], 1);
    d_col[p] = ei[e];
}

// ---------------- GEMM: out[m][n] = dinv[m] * sum_k X[m][k] * W[k][n] ----------------
// X: [NN][128] row-major, W: [128][BN] row-major.
template <int BN>
__global__ void __launch_bounds__(256) gemm_kernel(const float* __restrict__ X,
                                                   const float* __restrict__ W,
                                                   float* __restrict__ out) {
    constexpr int BM = 64;
    constexpr int TN = BN / 16;  // 8 or 4
    constexpr int TM = 4;
    __shared__ float As[64][64];
    __shared__ float Bs[64][BN];

    const int t = threadIdx.x;
    const int rb = blockIdx.x * BM;
    const int tx = t % 16;
    const int ty = t / 16;

    float acc[TM][TN];
#pragma unroll
    for (int i = 0; i < TM; i++)
#pragma unroll
        for (int j = 0; j < TN; j++) acc[i][j] = 0.f;

    for (int kc = 0; kc < 128; kc += 64) {
        // load A tile (64 rows x 64 cols)
        {
            int col4 = (t % 16) * 4;
            int r0 = t / 16;
#pragma unroll
            for (int p = 0; p < 4; p++) {
                int r = r0 + p * 16;
                int grow = rb + r;
                float4 v = make_float4(0.f, 0.f, 0.f, 0.f);
                if (grow < NN)
                    v = *(const float4*)(X + (size_t)grow * 128 + kc + col4);
                *(float4*)&As[r][col4] = v;
            }
        }
        // load B tile (64 x BN)
        {
            constexpr int C4 = BN / 4;        // 32 or 16 float4 per row
            constexpr int KP = 256 / C4;      // 8 or 16 rows per pass
            int n4 = (t % C4) * 4;
            int k0 = t / C4;
#pragma unroll
            for (int k = k0; k < 64; k += KP) {
                *(float4*)&Bs[k][n4] = *(const float4*)(W + (size_t)(kc + k) * BN + n4);
            }
        }
        __syncthreads();

#pragma unroll 8
        for (int k = 0; k < 64; k++) {
            float a[TM], b[TN];
#pragma unroll
            for (int i = 0; i < TM; i++) a[i] = As[ty * TM + i][k];
#pragma unroll
            for (int j = 0; j < TN; j++) b[j] = Bs[k][tx * TN + j];
#pragma unroll
            for (int i = 0; i < TM; i++)
#pragma unroll
                for (int j = 0; j < TN; j++) acc[i][j] += a[i] * b[j];
        }
        __syncthreads();
    }

#pragma unroll
    for (int i = 0; i < TM; i++) {
        int grow = rb + ty * TM + i;
        if (grow < NN) {
            float di = d_dinv[grow];
#pragma unroll
            for (int j = 0; j < TN; j += 4) {
                float4 v;
                v.x = acc[i][j + 0] * di;
                v.y = acc[i][j + 1] * di;
                v.z = acc[i][j + 2] * di;
                v.w = acc[i][j + 3] * di;
                *(float4*)(out + (size_t)grow * BN + tx * TN + j) = v;
            }
        }
    }
}

// ---------------- aggregation: out[i] = relu(dinv[i]*(sum_{j->i} g[j] + g[i]) + b) ----------------
// one warp per node, lanes cover features with vector loads.
template <int F, bool RELU>
__global__ void __launch_bounds__(256) agg_kernel(const float* __restrict__ g,
                                                  const float* __restrict__ bias,
                                                  float* __restrict__ out) {
    int node = (blockIdx.x * 256 + threadIdx.x) >> 5;
    if (node >= NN) return;
    int lane = threadIdx.x & 31;
    constexpr int V = F / 32;  // 4 or 2

    float acc[V];
    {
        const float* p = g + (size_t)node * F + lane * V;  // self term
        if constexpr (V == 4) {
            float4 v = *(const float4*)p;
            acc[0] = v.x; acc[1] = v.y; acc[2] = v.z; acc[3] = v.w;
        } else {
            float2 v = *(const float2*)p;
            acc[0] = v.x; acc[1] = v.y;
        }
    }

    int e = d_off[node];
    const int end = d_off[node + 1];
    for (; e + 2 <= end; e += 2) {
        int s0 = d_col[e];
        int s1 = d_col[e + 1];
        const float* p0 = g + (size_t)s0 * F + lane * V;
        const float* p1 = g + (size_t)s1 * F + lane * V;
        if constexpr (V == 4) {
            float4 v0 = *(const float4*)p0;
            float4 v1 = *(const float4*)p1;
            acc[0] += v0.x + v1.x;
            acc[1] += v0.y + v1.y;
            acc[2] += v0.z + v1.z;
            acc[3] += v0.w + v1.w;
        } else {
            float2 v0 = *(const float2*)p0;
            float2 v1 = *(const float2*)p1;
            acc[0] += v0.x + v1.x;
            acc[1] += v0.y + v1.y;
        }
    }
    if (e < end) {
        int s0 = d_col[e];
        const float* p0 = g + (size_t)s0 * F + lane * V;
        if constexpr (V == 4) {
            float4 v0 = *(const float4*)p0;
            acc[0] += v0.x; acc[1] += v0.y; acc[2] += v0.z; acc[3] += v0.w;
        } else {
            float2 v0 = *(const float2*)p0;
            acc[0] += v0.x; acc[1] += v0.y;
        }
    }

    const float di = d_dinv[node];
    float* po = out + (size_t)node * F + lane * V;
    if constexpr (V == 4) {
        float4 b = *(const float4*)(bias + lane * 4);
        float4 o;
        o.x = acc[0] * di + b.x;
        o.y = acc[1] * di + b.y;
        o.z = acc[2] * di + b.z;
        o.w = acc[3] * di + b.w;
        if (RELU) {
            o.x = fmaxf(o.x, 0.f); o.y = fmaxf(o.y, 0.f);
            o.z = fmaxf(o.z, 0.f); o.w = fmaxf(o.w, 0.f);
        }
        *(float4*)po = o;
    } else {
        float2 b = *(const float2*)(bias + lane * 2);
        float2 o;
        o.x = acc[0] * di + b.x;
        o.y = acc[1] * di + b.y;
        if (RELU) { o.x = fmaxf(o.x, 0.f); o.y = fmaxf(o.y, 0.f); }
        *(float2*)po = o;
    }
}

// ---------------- launch ----------------
extern "C" void kernel_launch(void* const* d_in, const int* in_sizes, int n_in,
                              void* d_out, int out_size) {
    (void)in_sizes; (void)n_in; (void)out_size;
    const float* x   = (const float*)d_in[0];
    const int*   ei  = (const int*)d_in[1];
    const float* W1  = (const float*)d_in[2];
    const float* b1  = (const float*)d_in[3];
    const float* Wm1 = (const float*)d_in[4];
    const float* bm1 = (const float*)d_in[5];
    const float* Wm2 = (const float*)d_in[6];
    const float* bm2 = (const float*)d_in[7];
    const float* W2  = (const float*)d_in[8];
    const float* b2  = (const float*)d_in[9];
    float* out = (float*)d_out;

    float *hA, *hB;
    cudaGetSymbolAddress((void**)&hA, d_hA);
    cudaGetSymbolAddress((void**)&hB, d_hB);

    const int NBLK = (NN + 255) / 256;
    const int EBLK = (EE + 255) / 256;
    const int GB   = (NN + 63) / 64;
    const int AB   = (NN * 32 + 255) / 256;

    deg_init_kernel<<<NBLK, 256>>>();
    deg_count_kernel<<<EBLK, 256>>>(ei);
    dinv_kernel<<<NBLK, 256>>>();
    scan1_kernel<<<NB_SCAN, 1024>>>();
    scan2_kernel<<<1, 128>>>();
    scan3_kernel<<<NBLK, 256>>>();
    fill_kernel<<<EBLK, 256>>>(ei);

    // layer 1: x -> hA (g), agg -> hB
    gemm_kernel<128><<<GB, 256>>>(x, W1, hA);
    agg_kernel<128, true><<<AB, 256>>>(hA, b1, hB);
    // layer 2
    gemm_kernel<128><<<GB, 256>>>(hB, Wm1, hA);
    agg_kernel<128, true><<<AB, 256>>>(hA, bm1, hB);
    // layer 3
    gemm_kernel<128><<<GB, 256>>>(hB, Wm2, hA);
    agg_kernel<128, true><<<AB, 256>>>(hA, bm2, hB);
    // layer 4 (OUT=64, no relu)
    gemm_kernel<64><<<GB, 256>>>(hB, W2, hA);
    agg_kernel<64, false><<<AB, 256>>>(hA, b2, out);
}

// round 3
// speedup vs baseline: 1.2637x; 1.2637x over previous
#include <cuda_runtime.h>
#include <cstdint>
#include <cstddef>

#define NN 100000
#define EE 1600000
#define NB_SCAN ((NN + 1023) / 1024)   // 98

// ---------------- device scratch (no allocations allowed) ----------------
__device__ int   d_indeg[NN];
__device__ float d_dinv[NN];
__device__ int   d_scan[NN];
__device__ int   d_bsum[128];
__device__ int   d_bexcl[128];
__device__ int   d_off[NN + 1];
__device__ int   d_cur[NN];
__device__ int   d_col[EE];
__device__ float d_hA[(size_t)NN * 128];
__device__ float d_hB[(size_t)NN * 128];

// ---------------- preprocessing ----------------
__global__ void deg_init_kernel() {
    int i = blockIdx.x * blockDim.x + threadIdx.x;
    if (i < NN) d_indeg[i] = 0;
}

__global__ void deg_count_kernel(const int* __restrict__ ei) {
    int e = blockIdx.x * blockDim.x + threadIdx.x;
    if (e < EE) atomicAdd(&d_indeg[ei[EE + e]], 1);
}

__global__ void dinv_kernel() {
    int i = blockIdx.x * blockDim.x + threadIdx.x;
    if (i < NN) d_dinv[i] = rsqrtf((float)(d_indeg[i] + 1));
}

// block-wise inclusive scan of indeg
__global__ void scan1_kernel() {
    __shared__ int sh[1024];
    int t = threadIdx.x;
    int i = blockIdx.x * 1024 + t;
    int v = (i < NN) ? d_indeg[i] : 0;
    sh[t] = v;
    __syncthreads();
    for (int s = 1; s < 1024; s <<= 1) {
        int add = (t >= s) ? sh[t - s] : 0;
        __syncthreads();
        sh[t] += add;
        __syncthreads();
    }
    if (i < NN) d_scan[i] = sh[t];
    if (t == 1023) d_bsum[blockIdx.x] = sh[1023];
}

// exclusive scan of block sums (single block)
__global__ void scan2_kernel() {
    __shared__ int sh[128];
    int t = threadIdx.x;
    int v = (t < NB_SCAN) ? d_bsum[t] : 0;
    sh[t] = v;
    __syncthreads();
    for (int s = 1; s < 128; s <<= 1) {
        int add = (t >= s) ? sh[t - s] : 0;
        __syncthreads();
        sh[t] += add;
        __syncthreads();
    }
    if (t < NB_SCAN) d_bexcl[t] = sh[t] - v;
}

__global__ void scan3_kernel() {
    int i = blockIdx.x * blockDim.x + threadIdx.x;
    if (i >= NN) return;
    int off = d_scan[i] - d_indeg[i] + d_bexcl[i >> 10];
    d_off[i] = off;
    d_cur[i] = off;
    if (i == NN - 1) d_off[NN] = off + d_indeg[i];
}

__global__ void fill_kernel(const int* __restrict__ ei) {
    int e = blockIdx.x * blockDim.x + threadIdx.x;
    if (e >= EE) return;
    int dst = ei[EE + e];
    int p = atomicAdd(&d_cur[dst], 1);
    d_col[p] = ei[e];
}

// ---------------- tf32 tensor-core GEMM ----------------
// out[m][n] = dinv[m] * sum_k X[m][k] * W[k][n]
// X: [NN][128] row-major, W: [128][BN] row-major.

__device__ __forceinline__ uint32_t f2tf(float f) {
    uint32_t u;
    asm("cvt.rna.tf32.f32 %0, %1;" : "=r"(u) : "f"(f));
    return u;
}

__device__ __forceinline__ void mma_tf32(float* c, const uint32_t* a,
                                         uint32_t b0, uint32_t b1) {
    asm volatile(
        "mma.sync.aligned.m16n8k8.row.col.f32.tf32.tf32.f32 "
        "{%0,%1,%2,%3}, {%4,%5,%6,%7}, {%8,%9}, {%0,%1,%2,%3};\n"
        : "+f"(c[0]), "+f"(c[1]), "+f"(c[2]), "+f"(c[3])
        : "r"(a[0]), "r"(a[1]), "r"(a[2]), "r"(a[3]), "r"(b0), "r"(b1));
}

template <int BN>
__global__ void __launch_bounds__(256) gemm_tc(const float* __restrict__ X,
                                               const float* __restrict__ W,
                                               float* __restrict__ out) {
    constexpr int BM = 64;
    constexpr int AS = 132;        // padded stride (conflict-free fragments)
    constexpr int WS = BN + 4;
    constexpr int NT = BN / 32;    // n-tiles per warp (4 or 2)

    extern __shared__ uint32_t sh[];
    uint32_t* As = sh;                  // [64][AS]
    uint32_t* Ws = sh + 64 * AS;        // [128][WS]

    const int t = threadIdx.x;
    const int w = t >> 5;
    const int lane = t & 31;
    const int g  = lane >> 2;    // 0..7
    const int tg = lane & 3;     // 0..3
    const int rb = blockIdx.x * BM;

    // stage W (128 x BN), converted to tf32
    {
        constexpr int TOT = 128 * (BN / 4);
        for (int i = t; i < TOT; i += 256) {
            int r  = i / (BN / 4);
            int c4 = (i % (BN / 4)) * 4;
            float4 v = *(const float4*)(W + (size_t)r * BN + c4);
            uint32_t* dst = Ws + r * WS + c4;
            dst[0] = f2tf(v.x); dst[1] = f2tf(v.y);
            dst[2] = f2tf(v.z); dst[3] = f2tf(v.w);
        }
    }
    // stage X tile (64 x 128)
    {
        for (int i = t; i < 64 * 32; i += 256) {
            int r  = i >> 5;
            int c4 = (i & 31) * 4;
            int grow = rb + r;
            float4 v = make_float4(0.f, 0.f, 0.f, 0.f);
            if (grow < NN) v = *(const float4*)(X + (size_t)grow * 128 + c4);
            uint32_t* dst = As + r * AS + c4;
            dst[0] = f2tf(v.x); dst[1] = f2tf(v.y);
            dst[2] = f2tf(v.z); dst[3] = f2tf(v.w);
        }
    }
    __syncthreads();

    // warp tile: 32 rows x (BN/4) cols
    const int m0 = (w & 1) * 32;
    const int n0 = (w >> 1) * (BN / 4);

    float acc[2][NT][4];
#pragma unroll
    for (int mt = 0; mt < 2; mt++)
#pragma unroll
        for (int nt = 0; nt < NT; nt++)
#pragma unroll
            for (int i = 0; i < 4; i++) acc[mt][nt][i] = 0.f;

#pragma unroll
    for (int k8 = 0; k8 < 128; k8 += 8) {
        uint32_t a[2][4];
#pragma unroll
        for (int mt = 0; mt < 2; mt++) {
            int r = m0 + mt * 16;
            a[mt][0] = As[(r + g) * AS + k8 + tg];
            a[mt][1] = As[(r + g + 8) * AS + k8 + tg];
            a[mt][2] = As[(r + g) * AS + k8 + tg + 4];
            a[mt][3] = As[(r + g + 8) * AS + k8 + tg + 4];
        }
#pragma unroll
        for (int nt = 0; nt < NT; nt++) {
            uint32_t b0 = Ws[(k8 + tg) * WS + n0 + nt * 8 + g];
            uint32_t b1 = Ws[(k8 + tg + 4) * WS + n0 + nt * 8 + g];
#pragma unroll
            for (int mt = 0; mt < 2; mt++)
                mma_tf32(acc[mt][nt], a[mt], b0, b1);
        }
    }

    // epilogue: scale by dinv[row], store
#pragma unroll
    for (int mt = 0; mt < 2; mt++) {
        int r0 = rb + m0 + mt * 16 + g;
        int r1 = r0 + 8;
        float di0 = (r0 < NN) ? d_dinv[r0] : 0.f;
        float di1 = (r1 < NN) ? d_dinv[r1] : 0.f;
#pragma unroll
        for (int nt = 0; nt < NT; nt++) {
            int c = n0 + nt * 8 + 2 * tg;
            if (r0 < NN) {
                float2 v = make_float2(acc[mt][nt][0] * di0, acc[mt][nt][1] * di0);
                *(float2*)(out + (size_t)r0 * BN + c) = v;
            }
            if (r1 < NN) {
                float2 v = make_float2(acc[mt][nt][2] * di1, acc[mt][nt][3] * di1);
                *(float2*)(out + (size_t)r1 * BN + c) = v;
            }
        }
    }
}

// ---------------- aggregation: out[i] = relu(dinv[i]*(sum_{j->i} g[j] + g[i]) + b) ----------------
template <int F, bool RELU>
__global__ void __launch_bounds__(256) agg_kernel(const float* __restrict__ g,
                                                  const float* __restrict__ bias,
                                                  float* __restrict__ out) {
    int node = (blockIdx.x * 256 + threadIdx.x) >> 5;
    if (node >= NN) return;
    int lane = threadIdx.x & 31;
    constexpr int V = F / 32;  // 4 or 2

    float acc[V];
    {
        const float* p = g + (size_t)node * F + lane * V;  // self term
        if constexpr (V == 4) {
            float4 v = *(const float4*)p;
            acc[0] = v.x; acc[1] = v.y; acc[2] = v.z; acc[3] = v.w;
        } else {
            float2 v = *(const float2*)p;
            acc[0] = v.x; acc[1] = v.y;
        }
    }

    int e = d_off[node];
    const int end = d_off[node + 1];
    for (; e + 2 <= end; e += 2) {
        int s0 = d_col[e];
        int s1 = d_col[e + 1];
        const float* p0 = g + (size_t)s0 * F + lane * V;
        const float* p1 = g + (size_t)s1 * F + lane * V;
        if constexpr (V == 4) {
            float4 v0 = *(const float4*)p0;
            float4 v1 = *(const float4*)p1;
            acc[0] += v0.x + v1.x;
            acc[1] += v0.y + v1.y;
            acc[2] += v0.z + v1.z;
            acc[3] += v0.w + v1.w;
        } else {
            float2 v0 = *(const float2*)p0;
            float2 v1 = *(const float2*)p1;
            acc[0] += v0.x + v1.x;
            acc[1] += v0.y + v1.y;
        }
    }
    if (e < end) {
        int s0 = d_col[e];
        const float* p0 = g + (size_t)s0 * F + lane * V;
        if constexpr (V == 4) {
            float4 v0 = *(const float4*)p0;
            acc[0] += v0.x; acc[1] += v0.y; acc[2] += v0.z; acc[3] += v0.w;
        } else {
            float2 v0 = *(const float2*)p0;
            acc[0] += v0.x; acc[1] += v0.y;
        }
    }

    const float di = d_dinv[node];
    float* po = out + (size_t)node * F + lane * V;
    if constexpr (V == 4) {
        float4 b = *(const float4*)(bias + lane * 4);
        float4 o;
        o.x = acc[0] * di + b.x;
        o.y = acc[1] * di + b.y;
        o.z = acc[2] * di + b.z;
        o.w = acc[3] * di + b.w;
        if (RELU) {
            o.x = fmaxf(o.x, 0.f); o.y = fmaxf(o.y, 0.f);
            o.z = fmaxf(o.z, 0.f); o.w = fmaxf(o.w, 0.f);
        }
        *(float4*)po = o;
    } else {
        float2 b = *(const float2*)(bias + lane * 2);
        float2 o;
        o.x = acc[0] * di + b.x;
        o.y = acc[1] * di + b.y;
        if (RELU) { o.x = fmaxf(o.x, 0.f); o.y = fmaxf(o.y, 0.f); }
        *(float2*)po = o;
    }
}

// ---------------- launch ----------------
extern "C" void kernel_launch(void* const* d_in, const int* in_sizes, int n_in,
                              void* d_out, int out_size) {
    (void)in_sizes; (void)n_in; (void)out_size;
    const float* x   = (const float*)d_in[0];
    const int*   ei  = (const int*)d_in[1];
    const float* W1  = (const float*)d_in[2];
    const float* b1  = (const float*)d_in[3];
    const float* Wm1 = (const float*)d_in[4];
    const float* bm1 = (const float*)d_in[5];
    const float* Wm2 = (const float*)d_in[6];
    const float* bm2 = (const float*)d_in[7];
    const float* W2  = (const float*)d_in[8];
    const float* b2  = (const float*)d_in[9];
    float* out = (float*)d_out;

    float *hA, *hB;
    cudaGetSymbolAddress((void**)&hA, d_hA);
    cudaGetSymbolAddress((void**)&hB, d_hB);

    const int NBLK = (NN + 255) / 256;
    const int EBLK = (EE + 255) / 256;
    const int GB   = (NN + 63) / 64;
    const int AB   = (NN * 32 + 255) / 256;

    // dynamic smem sizes: (64*132 + 128*(BN+4)) * 4 bytes
    const int SMEM128 = (64 * 132 + 128 * 132) * 4;  // 101376
    const int SMEM64  = (64 * 132 + 128 * 68)  * 4;  // 68608
    static bool attr_done = false;
    if (!attr_done) {
        cudaFuncSetAttribute(gemm_tc<128>, cudaFuncAttributeMaxDynamicSharedMemorySize, SMEM128);
        cudaFuncSetAttribute(gemm_tc<64>,  cudaFuncAttributeMaxDynamicSharedMemorySize, SMEM64);
        attr_done = true;
    }

    deg_init_kernel<<<NBLK, 256>>>();
    deg_count_kernel<<<EBLK, 256>>>(ei);
    dinv_kernel<<<NBLK, 256>>>();
    scan1_kernel<<<NB_SCAN, 1024>>>();
    scan2_kernel<<<1, 128>>>();
    scan3_kernel<<<NBLK, 256>>>();
    fill_kernel<<<EBLK, 256>>>(ei);

    // layer 1: x -> hA (g), agg -> hB
    gemm_tc<128><<<GB, 256, SMEM128>>>(x, W1, hA);
    agg_kernel<128, true><<<AB, 256>>>(hA, b1, hB);
    // layer 2
    gemm_tc<128><<<GB, 256, SMEM128>>>(hB, Wm1, hA);
    agg_kernel<128, true><<<AB, 256>>>(hA, bm1, hB);
    // layer 3
    gemm_tc<128><<<GB, 256, SMEM128>>>(hB, Wm2, hA);
    agg_kernel<128, true><<<AB, 256>>>(hA, bm2, hB);
    // layer 4 (OUT=64, no relu)
    gemm_tc<64><<<GB, 256, SMEM64>>>(hB, W2, hA);
    agg_kernel<64, false><<<AB, 256>>>(hA, b2, out);
}